// round 11
// baseline (speedup 1.0000x reference)
#include <cuda_runtime.h>
#include <cstdint>

#define K_NEIGH 20
#define THRES 0.5f
#define WPB 8
#define LCAP 16
#define SCAP 128
#define PIVOT 0.012f

// One warp per row of the (B*N, N) fp32 distance matrix. Output dtype f32.
//
// Key = ((float_bits(x)+1) << 32) | col : unique; ascending key order ==
// (value asc, col asc) == jax.lax.top_k(-x, 20) stable output order.
//
// Fast path:
//   1) deep-batched screened filter: 8 independent LDG.128 per lane per
//      iteration (4 KB/warp in flight), 8 independent FMIN trees, two
//      16-element screens -> inspect only groups containing x < PIVOT
//   2) warp-scan compaction of per-lane candidates into shared memory
//   3) rank selection: each candidate counts smaller keys over shared,
//      rank < 20 scatters directly to out[rank].
// Fallback (exact, any input): 20 rounds of bounded warp-min over the full
// row — taken on lane overflow, C < 20, or C > SCAP.

__device__ __forceinline__ unsigned long long warp_min_u64(unsigned long long m) {
    #pragma unroll
    for (int off = 16; off > 0; off >>= 1) {
        unsigned long long o = __shfl_xor_sync(0xFFFFFFFFu, m, off);
        if (o < m) m = o;
    }
    return m;
}

__global__ void __launch_bounds__(WPB * 32)
knn_thres_kernel(const float* __restrict__ x, float* __restrict__ out,
                 int N, int rows) {
    __shared__ unsigned long long cand[WPB][SCAP];

    const int warp = threadIdx.x >> 5;
    const int lane = threadIdx.x & 31;
    const int row  = blockIdx.x * WPB + warp;
    if (row >= rows) return;

    const float* __restrict__ xrow = x + (size_t)row * (size_t)N;

    unsigned long long loc[LCAP];
    int cl = 0;

    const int nvec = N >> 2;
    const float4* __restrict__ xv = (const float4*)xrow;

    // push all elements of one float4 that pass the pivot (vector pre-screened)
    auto push4 = [&](float4 v, int vecidx, float mv) {
        if (mv < PIVOT) {
            float vs[4] = {v.x, v.y, v.z, v.w};
            const int base = vecidx << 2;
            #pragma unroll
            for (int j = 0; j < 4; j++) {
                if (vs[j] < PIVOT) {
                    if (cl < LCAP) {
                        unsigned int bits = __float_as_uint(vs[j]) + 1u;
                        loc[cl] = ((unsigned long long)bits << 32)
                                  | (unsigned int)(base + j);
                    }
                    cl++;
                }
            }
        }
    };

    // ---- Phase 1: deep-batched screened filter (8 vectors/lane/iter) ----
    const int nchunks = nvec >> 8;              // 8 vectors x 32 lanes per chunk
    for (int g = 0; g < nchunks; g++) {
        const int i0 = (g << 8) + lane;
        float4 v[8];
        #pragma unroll
        for (int j = 0; j < 8; j++)             // 8 independent LDG.128, front-batched
            v[j] = xv[i0 + (j << 5)];
        float m[8];
        #pragma unroll
        for (int j = 0; j < 8; j++)             // 8 independent min trees
            m[j] = fminf(fminf(v[j].x, v[j].y), fminf(v[j].z, v[j].w));
        const float s0 = fminf(fminf(m[0], m[1]), fminf(m[2], m[3]));
        const float s1 = fminf(fminf(m[4], m[5]), fminf(m[6], m[7]));
        if (s0 < PIVOT) {
            #pragma unroll
            for (int j = 0; j < 4; j++) push4(v[j], i0 + (j << 5), m[j]);
        }
        if (s1 < PIVOT) {
            #pragma unroll
            for (int j = 4; j < 8; j++) push4(v[j], i0 + (j << 5), m[j]);
        }
    }
    // remainder vectors (nvec % 256 != 0; not hit for N = 4096)
    for (int i = lane + (nchunks << 8); i < nvec; i += 32) {
        float4 v = xv[i];
        float mv = fminf(fminf(v.x, v.y), fminf(v.z, v.w));
        push4(v, i, mv);
    }
    // scalar tail (N % 4 != 0; not hit for N = 4096)
    for (int i = (nvec << 2) + lane; i < N; i += 32) {
        float v = xrow[i];
        if (v < PIVOT) {
            if (cl < LCAP) {
                unsigned int bits = __float_as_uint(v) + 1u;
                loc[cl] = ((unsigned long long)bits << 32) | (unsigned int)i;
            }
            cl++;
        }
    }

    // ---- warp scan: overflow check, total, exclusive offsets ----
    const unsigned ovf = __ballot_sync(0xFFFFFFFFu, cl > LCAP);
    int incl = cl;
    #pragma unroll
    for (int off = 1; off < 32; off <<= 1) {
        int o = __shfl_up_sync(0xFFFFFFFFu, incl, off);
        if (lane >= off) incl += o;
    }
    const int tot  = __shfl_sync(0xFFFFFFFFu, incl, 31);
    const int offs = incl - cl;
    const bool fast = (ovf == 0u) && (tot >= K_NEIGH) && (tot <= SCAP);

    const float self_idx = (float)(row % N);        // row index within batch
    float* __restrict__ orow = out + (size_t)row * K_NEIGH;

    if (fast) {
        // ---- Phase 2: compact into shared ----
        for (int t = 0; t < cl; t++)
            cand[warp][offs + t] = loc[t];
        __syncwarp();

        // ---- Phase 3: rank selection, direct scatter ----
        const int C = tot;
        const unsigned long long* __restrict__ cw = cand[warp];
        for (int s = lane; s < C; s += 32) {
            const unsigned long long k = cw[s];
            int rank = 0;
            #pragma unroll 4
            for (int j = 0; j < C; j++)
                rank += (cw[j] < k);
            if (rank < K_NEIGH) {
                unsigned int bits = (unsigned int)(k >> 32) - 1u;
                float val = __uint_as_float(bits);
                float idx = (float)(unsigned int)(k & 0xFFFFFFFFu);
                orow[rank] = (val > THRES) ? self_idx : idx;
            }
        }
    } else {
        // ---- Exact fallback: 20 bounded warp-min rounds over full row ----
        unsigned long long prev = 0ULL;             // all keys > 0 (bits+1)
        for (int sel = 0; sel < K_NEIGH; sel++) {
            unsigned long long m = ~0ULL;
            for (int i = lane; i < N; i += 32) {
                unsigned int bits = __float_as_uint(xrow[i]) + 1u;
                unsigned long long k =
                    ((unsigned long long)bits << 32) | (unsigned int)i;
                if (k > prev && k < m) m = k;
            }
            m = warp_min_u64(m);
            prev = m;
            if (lane == 0) {
                unsigned int bits = (unsigned int)(m >> 32) - 1u;
                float val = __uint_as_float(bits);
                float idx = (float)(unsigned int)(m & 0xFFFFFFFFu);
                orow[sel] = (val > THRES) ? self_idx : idx;
            }
        }
    }
}

extern "C" void kernel_launch(void* const* d_in, const int* in_sizes, int n_in,
                              void* d_out, int out_size) {
    // the distance matrix is by far the largest input
    int xi = 0;
    for (int i = 1; i < n_in; i++)
        if (in_sizes[i] > in_sizes[xi]) xi = i;

    const float* x = (const float*)d_in[xi];
    float* out = (float*)d_out;

    const int rows = out_size / K_NEIGH;            // B * N  (= 65536 expected)
    const int N    = in_sizes[xi] / rows;           // num points (= 4096 expected)

    const int blocks = (rows + WPB - 1) / WPB;
    knn_thres_kernel<<<blocks, WPB * 32>>>(x, out, N, rows);
}